// round 2
// baseline (speedup 1.0000x reference)
#include <cuda_runtime.h>

// ---------------- problem constants ----------------
#define HH 128
#define MM 64
#define GG 512
#define MAXN 50000
#define NHH (MAXN * HH)

// ---------------- device scratch (referenced directly, no symbol lookup) ----------------
__device__ float g_xh[NHH];
__device__ float g_agg1[NHH];
__device__ float g_agg2[NHH];
__device__ float g_c[NHH];
__device__ float g_ha[NHH];
__device__ float g_hb[NHH];
__device__ float g_on[NHH];
__device__ float g_gsum[GG * HH];
__device__ float g_gsq[GG * HH];
__device__ float g_gcnt[GG];

// ---------------- helpers ----------------
__device__ __forceinline__ float f4get(const float4& v, int i) {
    return i == 0 ? v.x : (i == 1 ? v.y : (i == 2 ? v.z : v.w));
}

// sel: 0 agg1, 1 agg2, 2 gsum+gsq+gcnt
__global__ void k_zero(int sel, int n) {
    int i = blockIdx.x * blockDim.x + threadIdx.x;
    if (sel == 0) { if (i < n) g_agg1[i] = 0.f; }
    else if (sel == 1) { if (i < n) g_agg2[i] = 0.f; }
    else {
        if (i < GG * HH) { g_gsum[i] = 0.f; g_gsq[i] = 0.f; }
        if (i < GG) g_gcnt[i] = 0.f;
    }
}

// ---------------- node GEMM: out = [swish](A @ W + b) [+ A] ----------------
// W stored [in=128][out=128] row-major. 16 rows per block, 128 threads.
template <bool SW, bool RES>
__global__ void k_gemm1(const float* __restrict__ A, const float* __restrict__ W,
                        const float* __restrict__ bias, float* __restrict__ out, int n) {
    __shared__ __align__(16) float As[16][HH];
    int c = threadIdx.x;
    int r0 = blockIdx.x * 16;
    int rows = n - r0; if (rows > 16) rows = 16;
    #pragma unroll
    for (int r = 0; r < 16; r++)
        As[r][c] = (r < rows) ? A[(size_t)(r0 + r) * HH + c] : 0.f;
    __syncthreads();
    float acc[16];
    #pragma unroll
    for (int r = 0; r < 16; r++) acc[r] = 0.f;
    for (int k4 = 0; k4 < 32; k4++) {
        float w0 = W[(4 * k4 + 0) * HH + c];
        float w1 = W[(4 * k4 + 1) * HH + c];
        float w2 = W[(4 * k4 + 2) * HH + c];
        float w3 = W[(4 * k4 + 3) * HH + c];
        #pragma unroll
        for (int r = 0; r < 16; r++) {
            float4 a = *(const float4*)(&As[r][4 * k4]);
            acc[r] += a.x * w0;
            acc[r] += a.y * w1;
            acc[r] += a.z * w2;
            acc[r] += a.w * w3;
        }
    }
    float bc = bias[c];
    for (int r = 0; r < rows; r++) {
        float v = acc[r] + bc;
        if (SW) v = v / (1.f + expf(-v));
        if (RES) v += As[r][c];
        out[(size_t)(r0 + r) * HH + c] = v;
    }
}

// ---------------- out = A @ Wa + B @ Wb + bias [+ R] ----------------
template <bool RES>
__global__ void k_gemm2(const float* __restrict__ A, const float* __restrict__ Wa,
                        const float* __restrict__ B, const float* __restrict__ Wb,
                        const float* __restrict__ bias, const float* __restrict__ R,
                        float* __restrict__ out, int n) {
    __shared__ __align__(16) float As[16][HH];
    __shared__ __align__(16) float Bs[16][HH];
    int c = threadIdx.x;
    int r0 = blockIdx.x * 16;
    int rows = n - r0; if (rows > 16) rows = 16;
    #pragma unroll
    for (int r = 0; r < 16; r++) {
        As[r][c] = (r < rows) ? A[(size_t)(r0 + r) * HH + c] : 0.f;
        Bs[r][c] = (r < rows) ? B[(size_t)(r0 + r) * HH + c] : 0.f;
    }
    __syncthreads();
    float acc[16];
    #pragma unroll
    for (int r = 0; r < 16; r++) acc[r] = 0.f;
    for (int k4 = 0; k4 < 32; k4++) {
        float wa0 = Wa[(4 * k4 + 0) * HH + c];
        float wa1 = Wa[(4 * k4 + 1) * HH + c];
        float wa2 = Wa[(4 * k4 + 2) * HH + c];
        float wa3 = Wa[(4 * k4 + 3) * HH + c];
        float wb0 = Wb[(4 * k4 + 0) * HH + c];
        float wb1 = Wb[(4 * k4 + 1) * HH + c];
        float wb2 = Wb[(4 * k4 + 2) * HH + c];
        float wb3 = Wb[(4 * k4 + 3) * HH + c];
        #pragma unroll
        for (int r = 0; r < 16; r++) {
            float4 a = *(const float4*)(&As[r][4 * k4]);
            float4 b = *(const float4*)(&Bs[r][4 * k4]);
            acc[r] += a.x * wa0 + b.x * wb0;
            acc[r] += a.y * wa1 + b.y * wb1;
            acc[r] += a.z * wa2 + b.z * wb2;
            acc[r] += a.w * wa3 + b.w * wb3;
        }
    }
    float bc = bias[c];
    for (int r = 0; r < rows; r++) {
        float v = acc[r] + bc;
        if (RES) v += R[(size_t)(r0 + r) * HH + c];
        out[(size_t)(r0 + r) * HH + c] = v;
    }
}

// ---------------- edge MLP + gather + scatter-add ----------------
// For each edge e: mid = feat[e] @ W1 (F x 64), h = mid @ W2 (64 x 128),
// agg[dst] += h * xh[src].  Warp processes EPW=4 edges; lane owns m=2*lane..+1
// in mid stage and j=4*lane..+3 in h stage. W1/W2 staged in shared.
template <int F>
__global__ void k_edge(const float* __restrict__ feat, const float* __restrict__ W1,
                       const float* __restrict__ W2, const int* __restrict__ ei,
                       float* __restrict__ agg, int E) {
    constexpr int FP = (F + 3) & ~3;
    constexpr int NW = 8;
    constexpr int EPW = 4;
    extern __shared__ float sh[];
    float* W1s   = sh;                       // FP * 64
    float* W2s   = W1s + FP * 64;            // 64 * 128
    float* featb = W2s + 64 * HH;            // NW * EPW * FP
    float* midb  = featb + NW * EPW * FP;    // NW * EPW * 64

    int tid = threadIdx.x, w = tid >> 5, lane = tid & 31;
    for (int i = tid; i < FP * 64; i += blockDim.x) W1s[i] = (i < F * 64) ? W1[i] : 0.f;
    for (int i = tid; i < 64 * HH; i += blockDim.x) W2s[i] = W2[i];
    __syncthreads();

    float* fb = featb + w * (EPW * FP);
    float* mb = midb + w * (EPW * 64);

    long long base = (long long)(blockIdx.x * NW + w) * EPW;
    long long stride = (long long)gridDim.x * NW * EPW;
    for (long long e0 = base; e0 < E; e0 += stride) {
        int ne = (E - e0 < EPW) ? (int)(E - e0) : EPW;
        // stage features (zero-padded to FP, zero rows for missing edges)
        for (int e = 0; e < EPW; e++) {
            float* fbe = fb + e * FP;
            if (e < ne) {
                const float* fr = feat + (size_t)(e0 + e) * F;
                for (int k = lane; k < F; k += 32) fbe[k] = fr[k];
                if (lane < FP - F) fbe[F + lane] = 0.f;
            } else {
                for (int k = lane; k < FP; k += 32) fbe[k] = 0.f;
            }
        }
        __syncwarp();
        // mid = feat @ W1 : lane owns m = 2*lane, 2*lane+1
        float2 acc[EPW];
        #pragma unroll
        for (int e = 0; e < EPW; e++) { acc[e].x = 0.f; acc[e].y = 0.f; }
        for (int k4 = 0; k4 < FP / 4; k4++) {
            float4 fv[EPW];
            #pragma unroll
            for (int e = 0; e < EPW; e++) fv[e] = *(const float4*)&fb[e * FP + 4 * k4];
            #pragma unroll
            for (int kk = 0; kk < 4; kk++) {
                float2 wv = *(const float2*)&W1s[(4 * k4 + kk) * 64 + 2 * lane];
                #pragma unroll
                for (int e = 0; e < EPW; e++) {
                    float fe = f4get(fv[e], kk);
                    acc[e].x += fe * wv.x;
                    acc[e].y += fe * wv.y;
                }
            }
        }
        #pragma unroll
        for (int e = 0; e < EPW; e++) *(float2*)&mb[e * 64 + 2 * lane] = acc[e];
        __syncwarp();
        // h = mid @ W2 : lane owns j = 4*lane .. 4*lane+3
        float4 hv[EPW];
        #pragma unroll
        for (int e = 0; e < EPW; e++) { hv[e].x = hv[e].y = hv[e].z = hv[e].w = 0.f; }
        for (int m4 = 0; m4 < 16; m4++) {
            float4 mm[EPW];
            #pragma unroll
            for (int e = 0; e < EPW; e++) mm[e] = *(const float4*)&mb[e * 64 + 4 * m4];
            #pragma unroll
            for (int kk = 0; kk < 4; kk++) {
                float4 wv = *(const float4*)&W2s[(4 * m4 + kk) * HH + 4 * lane];
                #pragma unroll
                for (int e = 0; e < EPW; e++) {
                    float me = f4get(mm[e], kk);
                    hv[e].x += me * wv.x;
                    hv[e].y += me * wv.y;
                    hv[e].z += me * wv.z;
                    hv[e].w += me * wv.w;
                }
            }
        }
        // epilogue: agg[dst] += h * xh[src]
        for (int e = 0; e < ne; e++) {
            long long ed = e0 + e;
            int src = ei[ed];
            int dst = ei[(size_t)E + ed];
            float4 xv = *(const float4*)&g_xh[(size_t)src * HH + 4 * lane];
            float* ag = agg + (size_t)dst * HH + 4 * lane;
            atomicAdd(ag + 0, hv[e].x * xv.x);
            atomicAdd(ag + 1, hv[e].y * xv.y);
            atomicAdd(ag + 2, hv[e].z * xv.z);
            atomicAdd(ag + 3, hv[e].w * xv.w);
        }
        __syncwarp();
    }
}

// ---------------- GraphNorm pieces ----------------
// pass 1: per-graph count + per-channel sum (count done by c==0 lanes)
__global__ void k_gsum(const float* __restrict__ h, const int* __restrict__ batch, int n) {
    int idx = blockIdx.x * blockDim.x + threadIdx.x;
    if (idx >= n * HH) return;
    int i = idx >> 7, c = idx & 127;
    int g = batch[i];
    if (c == 0) atomicAdd(&g_gcnt[g], 1.f);
    atomicAdd(&g_gsum[g * HH + c], h[idx]);
}

__global__ void k_center(const float* __restrict__ h, const int* __restrict__ batch,
                         const float* __restrict__ ms, int n) {
    int idx = blockIdx.x * blockDim.x + threadIdx.x;
    if (idx >= n * HH) return;
    int i = idx >> 7, c = idx & 127;
    int g = batch[i];
    float cnt = g_gcnt[g]; if (cnt < 1.f) cnt = 1.f;
    float mean = g_gsum[g * HH + c] / cnt;
    float o = h[idx] - mean * ms[c];
    g_on[idx] = o;
    atomicAdd(&g_gsq[g * HH + c], o * o);
}

__global__ void k_norm(const int* __restrict__ batch,
                       const float* __restrict__ w, const float* __restrict__ b, int n) {
    int idx = blockIdx.x * blockDim.x + threadIdx.x;
    if (idx >= n * HH) return;
    int i = idx >> 7, c = idx & 127;
    int g = batch[i];
    float cnt = g_gcnt[g]; if (cnt < 1.f) cnt = 1.f;
    float var = g_gsq[g * HH + c] / cnt;
    g_on[idx] = w[c] * g_on[idx] * rsqrtf(var + 1e-5f) + b[c];
}

// ---------------- launch ----------------
extern "C" void kernel_launch(void* const* d_in, const int* in_sizes, int n_in,
                              void* d_out, int out_size) {
    const float* x          = (const float*)d_in[0];
    const float* feature1   = (const float*)d_in[1];
    const float* feature2   = (const float*)d_in[2];
    const int*   edge_index = (const int*)d_in[3];
    const int*   batch      = (const int*)d_in[4];
    const float* lin_w        = (const float*)d_in[5];
    const float* lin_b        = (const float*)d_in[6];
    const float* f1_w1        = (const float*)d_in[7];
    const float* f1_w2        = (const float*)d_in[8];
    const float* f2_w1        = (const float*)d_in[9];
    const float* f2_w2        = (const float*)d_in[10];
    const float* conv1_rel_w  = (const float*)d_in[11];
    const float* conv1_rel_b  = (const float*)d_in[12];
    const float* conv1_root_w = (const float*)d_in[13];
    const float* conv2_rel_w  = (const float*)d_in[14];
    const float* conv2_rel_b  = (const float*)d_in[15];
    const float* conv2_root_w = (const float*)d_in[16];
    const float* lin1_w       = (const float*)d_in[17];
    const float* lin1_b       = (const float*)d_in[18];
    const float* lin2_w       = (const float*)d_in[19];
    const float* lin2_b       = (const float*)d_in[20];
    const float* lincat_w     = (const float*)d_in[21];
    const float* lincat_b     = (const float*)d_in[22];
    const float* norm_w       = (const float*)d_in[23];
    const float* norm_b       = (const float*)d_in[24];
    const float* norm_ms      = (const float*)d_in[25];
    const float* lins_w       = (const float*)d_in[26];
    const float* lins_b       = (const float*)d_in[27];
    const float* final_w      = (const float*)d_in[28];
    const float* final_b      = (const float*)d_in[29];

    int N_ = in_sizes[0] / HH;
    int E_ = in_sizes[3] / 2;

    // device-global scratch pointers: taken once via kernels referencing the
    // symbols directly; for kernels that take pointers we use the fact that
    // device globals have stable addresses obtainable with a tiny capture-safe
    // trick: launch with symbol-referencing kernels only. For pointer args we
    // still need addresses -> use cudaGetSymbolAddress (capture-safe, no alloc).
    static float *p_xh = nullptr, *p_agg1, *p_agg2, *p_c, *p_ha, *p_hb, *p_on;
    if (!p_xh) {
        cudaGetSymbolAddress((void**)&p_xh,   g_xh);
        cudaGetSymbolAddress((void**)&p_agg1, g_agg1);
        cudaGetSymbolAddress((void**)&p_agg2, g_agg2);
        cudaGetSymbolAddress((void**)&p_c,    g_c);
        cudaGetSymbolAddress((void**)&p_ha,   g_ha);
        cudaGetSymbolAddress((void**)&p_hb,   g_hb);
        cudaGetSymbolAddress((void**)&p_on,   g_on);
    }

    // dynamic shared sizes for the edge kernels
    const int FP1 = 148, FP2 = 24;
    int sme1 = (FP1 * 64 + 64 * HH + 8 * 4 * FP1 + 8 * 4 * 64) * 4;  // 97792 B
    int sme2 = (FP2 * 64 + 64 * HH + 8 * 4 * FP2 + 8 * 4 * 64) * 4;  // 50176 B
    static bool attr_done = false;
    if (!attr_done) {
        cudaFuncSetAttribute(k_edge<147>, cudaFuncAttributeMaxDynamicSharedMemorySize, sme1);
        cudaFuncSetAttribute(k_edge<21>,  cudaFuncAttributeMaxDynamicSharedMemorySize, sme2);
        attr_done = true;
    }

    int NH_ = N_ * HH;
    int gZ = (NH_ + 255) / 256;
    k_zero<<<gZ, 256>>>(0, NH_);
    k_zero<<<gZ, 256>>>(1, NH_);
    k_zero<<<(GG * HH + 255) / 256, 256>>>(2, NH_);

    int gB = (N_ + 15) / 16;

    // xh = swish(x @ lin_w + lin_b)
    k_gemm1<true, false><<<gB, 128>>>(x, lin_w, lin_b, p_xh, N_);

    // edge MLPs + scatter
    k_edge<147><<<1184, 256, sme1>>>(feature1, f1_w1, f1_w2, edge_index, p_agg1, E_);
    k_edge<21><<<1184, 256, sme2>>>(feature2, f2_w1, f2_w2, edge_index, p_agg2, E_);

    // conv1 / lin1  (h1 -> p_agg1 reuse)
    k_gemm2<false><<<gB, 128>>>(p_agg1, conv1_rel_w, p_xh, conv1_root_w, conv1_rel_b, nullptr, p_c, N_);
    k_gemm1<true, false><<<gB, 128>>>(p_c, lin1_w, lin1_b, p_agg1, N_);
    // conv2 / lin2  (h2 -> p_agg2 reuse)
    k_gemm2<false><<<gB, 128>>>(p_agg2, conv2_rel_w, p_xh, conv2_root_w, conv2_rel_b, nullptr, p_c, N_);
    k_gemm1<true, false><<<gB, 128>>>(p_c, lin2_w, lin2_b, p_agg2, N_);

    // h = cat(h1,h2) @ lincat + b + xh
    k_gemm2<true><<<gB, 128>>>(p_agg1, lincat_w, p_agg2, lincat_w + HH * HH, lincat_b, p_xh, p_ha, N_);

    // residual lins: h = swish(h@W+b) + h  (x3, ping-pong)
    k_gemm1<true, true><<<gB, 128>>>(p_ha, lins_w,               lins_b,           p_hb, N_);
    k_gemm1<true, true><<<gB, 128>>>(p_hb, lins_w + 1 * HH * HH, lins_b + 1 * HH,  p_ha, N_);
    k_gemm1<true, true><<<gB, 128>>>(p_ha, lins_w + 2 * HH * HH, lins_b + 2 * HH,  p_hb, N_);

    // GraphNorm
    k_gsum<<<gZ, 256>>>(p_hb, batch, N_);
    k_center<<<gZ, 256>>>(p_hb, batch, norm_ms, N_);
    k_norm<<<gZ, 256>>>(batch, norm_w, norm_b, N_);

    // final projection
    k_gemm1<false, false><<<gB, 128>>>(p_on, final_w, final_b, (float*)d_out, N_);
}

// round 3
// speedup vs baseline: 1.0496x; 1.0496x over previous
#include <cuda_runtime.h>
#include <cstdint>
#include <math.h>

// ---------------- problem constants ----------------
#define HH 128
#define GG 512
#define MAXN 50000
#define NHH (MAXN * HH)

// ---------------- device scratch ----------------
__device__ float g_xh[NHH];
__device__ float g_agg1[NHH];
__device__ float g_agg2[NHH];
__device__ float g_c[NHH];
__device__ float g_ha[NHH];
__device__ float g_hb[NHH];
__device__ float g_on[NHH];
__device__ float g_gsum[GG * HH];
__device__ float g_gsq[GG * HH];
__device__ float g_gcnt[GG];
__device__ float g_w12a_hi[128 * 147];
__device__ float g_w12a_lo[128 * 147];
__device__ float g_w12b_hi[128 * 21];
__device__ float g_w12b_lo[128 * 21];

// ---------------- tf32 helpers ----------------
__device__ __forceinline__ void split_tf32(float x, uint32_t& hi, uint32_t& lo) {
    asm("cvt.rna.tf32.f32 %0, %1;" : "=r"(hi) : "f"(x));
    float r = x - __uint_as_float(hi);
    asm("cvt.rna.tf32.f32 %0, %1;" : "=r"(lo) : "f"(r));
}

__device__ __forceinline__ void mma8(float* d, uint32_t a0, uint32_t a1, uint32_t a2,
                                     uint32_t a3, uint32_t b0, uint32_t b1) {
    asm volatile(
        "mma.sync.aligned.m16n8k8.row.col.f32.tf32.tf32.f32 "
        "{%0,%1,%2,%3}, {%4,%5,%6,%7}, {%8,%9}, {%0,%1,%2,%3};\n"
        : "+f"(d[0]), "+f"(d[1]), "+f"(d[2]), "+f"(d[3])
        : "r"(a0), "r"(a1), "r"(a2), "r"(a3), "r"(b0), "r"(b1));
}

// ---------------- misc kernels ----------------
__global__ void k_zero(int sel, int n) {
    int i = blockIdx.x * blockDim.x + threadIdx.x;
    if (sel == 0) { if (i < n) g_agg1[i] = 0.f; }
    else if (sel == 1) { if (i < n) g_agg2[i] = 0.f; }
    else {
        if (i < GG * HH) { g_gsum[i] = 0.f; g_gsq[i] = 0.f; }
        if (i < GG) g_gcnt[i] = 0.f;
    }
}

// W12[k][n] = sum_m W1[k][m] * W2[m][n]; store split n-major: out[n*F + k]
template <int F>
__global__ void k_w12(const float* __restrict__ W1, const float* __restrict__ W2,
                      float* __restrict__ ohi, float* __restrict__ olo) {
    int k = blockIdx.x, n = threadIdx.x;
    float acc = 0.f;
    for (int m = 0; m < 64; m++) acc += W1[k * 64 + m] * W2[m * 128 + n];
    uint32_t hi, lo;
    split_tf32(acc, hi, lo);
    ohi[n * F + k] = __uint_as_float(hi);
    olo[n * F + k] = __uint_as_float(lo);
}

// ---------------- tensor-core node GEMM ----------------
// out = [swish](A @ Wa [+ B @ Wb] + bias) [+ R]. All matrices [*,128], W [128][128] row-major (in x out).
template <bool DUAL, bool SW, bool RES>
__global__ __launch_bounds__(256, 1) void k_gemmT(
    const float* __restrict__ A, const float* __restrict__ Wa,
    const float* __restrict__ B, const float* __restrict__ Wb,
    const float* __restrict__ bias, const float* __restrict__ R,
    float* __restrict__ out, int n) {
    constexpr int AW = 132, WW = 134;
    extern __shared__ float sh[];
    float2* Ws = (float2*)sh;            // [128][WW] {hi,lo}, n-major
    float* As = sh + 2 * 128 * WW;       // [128][AW]
    int tid = threadIdx.x, w = tid >> 5, lane = tid & 31, g = lane >> 2, t = lane & 3;
    int r0 = blockIdx.x * 128;

    float acc[8][2][4];
    #pragma unroll
    for (int mf = 0; mf < 8; mf++)
        #pragma unroll
        for (int nf = 0; nf < 2; nf++)
            #pragma unroll
            for (int i = 0; i < 4; i++) acc[mf][nf][i] = 0.f;

    const int NPASS = DUAL ? 2 : 1;
    for (int p = 0; p < NPASS; p++) {
        const float* Ain = p ? B : A;
        const float* Win = p ? Wb : Wa;
        __syncthreads();
        for (int i = tid; i < 128 * 128; i += 256) {
            int k = i >> 7, nn = i & 127;
            uint32_t hi, lo;
            split_tf32(Win[i], hi, lo);
            Ws[nn * WW + k] = make_float2(__uint_as_float(hi), __uint_as_float(lo));
        }
        for (int i = tid; i < 128 * 32; i += 256) {
            int r = i >> 5, c4 = i & 31;
            int row = r0 + r;
            float4 v = (row < n) ? ((const float4*)(Ain + (size_t)row * 128))[c4]
                                 : make_float4(0.f, 0.f, 0.f, 0.f);
            *(float4*)&As[r * AW + 4 * c4] = v;
        }
        __syncthreads();
        for (int ks = 0; ks < 16; ks++) {
            int kl = ks * 8;
            uint32_t bh[2][2], bl[2][2];
            #pragma unroll
            for (int nf = 0; nf < 2; nf++) {
                int nn = 16 * w + 8 * nf + g;
                float2 b0 = Ws[nn * WW + kl + t];
                float2 b1 = Ws[nn * WW + kl + t + 4];
                bh[nf][0] = __float_as_uint(b0.x); bl[nf][0] = __float_as_uint(b0.y);
                bh[nf][1] = __float_as_uint(b1.x); bl[nf][1] = __float_as_uint(b1.y);
            }
            #pragma unroll
            for (int mf = 0; mf < 8; mf++) {
                int r = mf * 16 + g;
                float a0 = As[r * AW + kl + t];
                float a1 = As[(r + 8) * AW + kl + t];
                float a2 = As[r * AW + kl + t + 4];
                float a3 = As[(r + 8) * AW + kl + t + 4];
                uint32_t ah[4], al[4];
                split_tf32(a0, ah[0], al[0]);
                split_tf32(a1, ah[1], al[1]);
                split_tf32(a2, ah[2], al[2]);
                split_tf32(a3, ah[3], al[3]);
                #pragma unroll
                for (int nf = 0; nf < 2; nf++) {
                    mma8(acc[mf][nf], al[0], al[1], al[2], al[3], bh[nf][0], bh[nf][1]);
                    mma8(acc[mf][nf], ah[0], ah[1], ah[2], ah[3], bl[nf][0], bl[nf][1]);
                    mma8(acc[mf][nf], ah[0], ah[1], ah[2], ah[3], bh[nf][0], bh[nf][1]);
                }
            }
        }
    }
    // epilogue direct from registers
    float2 bb[2];
    #pragma unroll
    for (int nf = 0; nf < 2; nf++) {
        int col = 16 * w + 8 * nf + 2 * t;
        bb[nf] = *(const float2*)&bias[col];
    }
    #pragma unroll
    for (int mf = 0; mf < 8; mf++) {
        #pragma unroll
        for (int half = 0; half < 2; half++) {
            int row = r0 + mf * 16 + g + 8 * half;
            if (row < n) {
                #pragma unroll
                for (int nf = 0; nf < 2; nf++) {
                    int col = 16 * w + 8 * nf + 2 * t;
                    float vx = acc[mf][nf][2 * half + 0] + bb[nf].x;
                    float vy = acc[mf][nf][2 * half + 1] + bb[nf].y;
                    if (SW) { vx = vx / (1.f + expf(-vx)); vy = vy / (1.f + expf(-vy)); }
                    if (RES) {
                        float2 rv = *(const float2*)&R[(size_t)row * 128 + col];
                        vx += rv.x; vy += rv.y;
                    }
                    *(float2*)&out[(size_t)row * 128 + col] = make_float2(vx, vy);
                }
            }
        }
    }
}

// ---------------- tensor-core edge GEMM + gather/scatter ----------------
// f_tile[128 x 128] = feat_tile[128 x F] @ W12[F x 128]; agg[dst] += f ⊙ xh[src]
template <int F>
__global__ __launch_bounds__(256, 1) void k_edgeT(
    const float* __restrict__ feat, const float* __restrict__ bhi,
    const float* __restrict__ blo, const int* __restrict__ ei,
    const float* __restrict__ xh, float* __restrict__ agg, int E) {
    constexpr int KTOT = (F == 147) ? 152 : 32;
    constexpr int CS = (F == 147) ? 80 : 32;
    constexpr int NCH = (KTOT + CS - 1) / CS;
    constexpr int AW = (F == 147) ? 84 : 36;
    constexpr int BW = (F == 147) ? 166 : 38;
    extern __shared__ float sh[];
    float2* Bs = (float2*)sh;                       // [128][BW] {hi,lo}, n-major
    float* As = sh + 2 * 128 * BW;                  // [128][AW]
    float* fs = (F == 147) ? As : As + 128 * AW;    // [64][132]
    float* send = (F == 147) ? (As + 128 * AW) : (fs + 64 * 132);
    int* srcs = (int*)send;
    int* dsts = srcs + 128;

    int tid = threadIdx.x, w = tid >> 5, lane = tid & 31, g = lane >> 2, t = lane & 3;

    for (int i = tid; i < 128 * BW; i += 256) Bs[i] = make_float2(0.f, 0.f);
    __syncthreads();
    for (int i = tid; i < 128 * F; i += 256) {
        int n = i / F, k = i % F;
        Bs[n * BW + k] = make_float2(bhi[i], blo[i]);
    }

    int ntiles = (E + 127) >> 7;
    for (int tile = blockIdx.x; tile < ntiles; tile += gridDim.x) {
        float acc[8][2][4];
        #pragma unroll
        for (int mf = 0; mf < 8; mf++)
            #pragma unroll
            for (int nf = 0; nf < 2; nf++)
                #pragma unroll
                for (int i = 0; i < 4; i++) acc[mf][nf][i] = 0.f;

        if (tid < 128) {
            int ed = tile * 128 + tid;
            srcs[tid] = (ed < E) ? ei[ed] : 0;
            dsts[tid] = (ed < E) ? ei[(size_t)E + ed] : 0;
        }
        for (int c = 0; c < NCH; c++) {
            __syncthreads();
            for (int i = tid; i < 128 * CS; i += 256) {
                int r = i / CS, kl = i % CS;
                int k = c * CS + kl;
                int ed = tile * 128 + r;
                As[r * AW + kl] = (ed < E && k < F) ? feat[(size_t)ed * F + k] : 0.f;
            }
            __syncthreads();
            int ksteps = (c == NCH - 1) ? (KTOT - c * CS) / 8 : CS / 8;
            for (int ks = 0; ks < ksteps; ks++) {
                int kl = ks * 8;
                int kg = c * CS + kl;
                uint32_t bh[2][2], bl[2][2];
                #pragma unroll
                for (int nf = 0; nf < 2; nf++) {
                    int nn = 16 * w + 8 * nf + g;
                    float2 b0 = Bs[nn * BW + kg + t];
                    float2 b1 = Bs[nn * BW + kg + t + 4];
                    bh[nf][0] = __float_as_uint(b0.x); bl[nf][0] = __float_as_uint(b0.y);
                    bh[nf][1] = __float_as_uint(b1.x); bl[nf][1] = __float_as_uint(b1.y);
                }
                #pragma unroll
                for (int mf = 0; mf < 8; mf++) {
                    int r = mf * 16 + g;
                    float a0 = As[r * AW + kl + t];
                    float a1 = As[(r + 8) * AW + kl + t];
                    float a2 = As[r * AW + kl + t + 4];
                    float a3 = As[(r + 8) * AW + kl + t + 4];
                    uint32_t ah[4], al[4];
                    split_tf32(a0, ah[0], al[0]);
                    split_tf32(a1, ah[1], al[1]);
                    split_tf32(a2, ah[2], al[2]);
                    split_tf32(a3, ah[3], al[3]);
                    #pragma unroll
                    for (int nf = 0; nf < 2; nf++) {
                        mma8(acc[mf][nf], al[0], al[1], al[2], al[3], bh[nf][0], bh[nf][1]);
                        mma8(acc[mf][nf], ah[0], ah[1], ah[2], ah[3], bl[nf][0], bl[nf][1]);
                        mma8(acc[mf][nf], ah[0], ah[1], ah[2], ah[3], bh[nf][0], bh[nf][1]);
                    }
                }
            }
        }
        // epilogue: per 64-row half, stage f to smem, then vector-atomic scatter
        #pragma unroll
        for (int h = 0; h < 2; h++) {
            __syncthreads();
            #pragma unroll
            for (int mf = 4 * h; mf < 4 * h + 4; mf++) {
                int rb = mf * 16 + g - h * 64;
                #pragma unroll
                for (int nf = 0; nf < 2; nf++) {
                    int col = 16 * w + 8 * nf + 2 * t;
                    *(float2*)&fs[rb * 132 + col] =
                        make_float2(acc[mf][nf][0], acc[mf][nf][1]);
                    *(float2*)&fs[(rb + 8) * 132 + col] =
                        make_float2(acc[mf][nf][2], acc[mf][nf][3]);
                }
            }
            __syncthreads();
            int rl = h * 64 + w * 8 + g;
            int ed = tile * 128 + rl;
            if (ed < E) {
                int s = srcs[rl], d = dsts[rl];
                const float4* xr = (const float4*)(xh + (size_t)s * 128);
                float4* ar = (float4*)(agg + (size_t)d * 128);
                #pragma unroll
                for (int i = 0; i < 8; i++) {
                    int c4 = t + 4 * i;
                    float4 f = *(float4*)&fs[(rl - h * 64) * 132 + 4 * c4];
                    float4 xv = xr[c4];
                    atomicAdd(ar + c4,
                              make_float4(f.x * xv.x, f.y * xv.y, f.z * xv.z, f.w * xv.w));
                }
            }
        }
        __syncthreads();
    }
}

// ---------------- GraphNorm pieces (unchanged, passing) ----------------
__global__ void k_gsum(const float* __restrict__ h, const int* __restrict__ batch, int n) {
    int idx = blockIdx.x * blockDim.x + threadIdx.x;
    if (idx >= n * HH) return;
    int i = idx >> 7, c = idx & 127;
    int g = batch[i];
    if (c == 0) atomicAdd(&g_gcnt[g], 1.f);
    atomicAdd(&g_gsum[g * HH + c], h[idx]);
}

__global__ void k_center(const float* __restrict__ h, const int* __restrict__ batch,
                         const float* __restrict__ ms, int n) {
    int idx = blockIdx.x * blockDim.x + threadIdx.x;
    if (idx >= n * HH) return;
    int i = idx >> 7, c = idx & 127;
    int g = batch[i];
    float cnt = g_gcnt[g]; if (cnt < 1.f) cnt = 1.f;
    float mean = g_gsum[g * HH + c] / cnt;
    float o = h[idx] - mean * ms[c];
    g_on[idx] = o;
    atomicAdd(&g_gsq[g * HH + c], o * o);
}

__global__ void k_norm(const int* __restrict__ batch,
                       const float* __restrict__ w, const float* __restrict__ b, int n) {
    int idx = blockIdx.x * blockDim.x + threadIdx.x;
    if (idx >= n * HH) return;
    int i = idx >> 7, c = idx & 127;
    int g = batch[i];
    float cnt = g_gcnt[g]; if (cnt < 1.f) cnt = 1.f;
    float var = g_gsq[g * HH + c] / cnt;
    g_on[idx] = w[c] * g_on[idx] * rsqrtf(var + 1e-5f) + b[c];
}

// ---------------- launch ----------------
extern "C" void kernel_launch(void* const* d_in, const int* in_sizes, int n_in,
                              void* d_out, int out_size) {
    const float* x          = (const float*)d_in[0];
    const float* feature1   = (const float*)d_in[1];
    const float* feature2   = (const float*)d_in[2];
    const int*   edge_index = (const int*)d_in[3];
    const int*   batch      = (const int*)d_in[4];
    const float* lin_w        = (const float*)d_in[5];
    const float* lin_b        = (const float*)d_in[6];
    const float* f1_w1        = (const float*)d_in[7];
    const float* f1_w2        = (const float*)d_in[8];
    const float* f2_w1        = (const float*)d_in[9];
    const float* f2_w2        = (const float*)d_in[10];
    const float* conv1_rel_w  = (const float*)d_in[11];
    const float* conv1_rel_b  = (const float*)d_in[12];
    const float* conv1_root_w = (const float*)d_in[13];
    const float* conv2_rel_w  = (const float*)d_in[14];
    const float* conv2_rel_b  = (const float*)d_in[15];
    const float* conv2_root_w = (const float*)d_in[16];
    const float* lin1_w       = (const float*)d_in[17];
    const float* lin1_b       = (const float*)d_in[18];
    const float* lin2_w       = (const float*)d_in[19];
    const float* lin2_b       = (const float*)d_in[20];
    const float* lincat_w     = (const float*)d_in[21];
    const float* lincat_b     = (const float*)d_in[22];
    const float* norm_w       = (const float*)d_in[23];
    const float* norm_b       = (const float*)d_in[24];
    const float* norm_ms      = (const float*)d_in[25];
    const float* lins_w       = (const float*)d_in[26];
    const float* lins_b       = (const float*)d_in[27];
    const float* final_w      = (const float*)d_in[28];
    const float* final_b      = (const float*)d_in[29];

    int N_ = in_sizes[0] / HH;
    int E_ = in_sizes[3] / 2;

    static float *p_xh = nullptr, *p_agg1, *p_agg2, *p_c, *p_ha, *p_hb, *p_on;
    static float *p_wa_hi, *p_wa_lo, *p_wb_hi, *p_wb_lo;
    if (!p_xh) {
        cudaGetSymbolAddress((void**)&p_xh,   g_xh);
        cudaGetSymbolAddress((void**)&p_agg1, g_agg1);
        cudaGetSymbolAddress((void**)&p_agg2, g_agg2);
        cudaGetSymbolAddress((void**)&p_c,    g_c);
        cudaGetSymbolAddress((void**)&p_ha,   g_ha);
        cudaGetSymbolAddress((void**)&p_hb,   g_hb);
        cudaGetSymbolAddress((void**)&p_on,   g_on);
        cudaGetSymbolAddress((void**)&p_wa_hi, g_w12a_hi);
        cudaGetSymbolAddress((void**)&p_wa_lo, g_w12a_lo);
        cudaGetSymbolAddress((void**)&p_wb_hi, g_w12b_hi);
        cudaGetSymbolAddress((void**)&p_wb_lo, g_w12b_lo);
    }

    const int sme1 = (2 * 128 * 166 + 128 * 84) * 4 + 1024;              // 215,040
    const int sme2 = (2 * 128 * 38 + 128 * 36 + 64 * 132) * 4 + 1024;    // 92,160
    const int smg  = (2 * 128 * 134 + 128 * 132) * 4;                    // 204,800
    static bool attr_done = false;
    if (!attr_done) {
        cudaFuncSetAttribute(k_edgeT<147>, cudaFuncAttributeMaxDynamicSharedMemorySize, sme1);
        cudaFuncSetAttribute(k_edgeT<21>,  cudaFuncAttributeMaxDynamicSharedMemorySize, sme2);
        cudaFuncSetAttribute(k_gemmT<false, true, false>,  cudaFuncAttributeMaxDynamicSharedMemorySize, smg);
        cudaFuncSetAttribute(k_gemmT<true, false, false>,  cudaFuncAttributeMaxDynamicSharedMemorySize, smg);
        cudaFuncSetAttribute(k_gemmT<true, false, true>,   cudaFuncAttributeMaxDynamicSharedMemorySize, smg);
        cudaFuncSetAttribute(k_gemmT<false, true, true>,   cudaFuncAttributeMaxDynamicSharedMemorySize, smg);
        cudaFuncSetAttribute(k_gemmT<false, false, false>, cudaFuncAttributeMaxDynamicSharedMemorySize, smg);
        attr_done = true;
    }

    int NH_ = N_ * HH;
    int gZ = (NH_ + 255) / 256;
    k_zero<<<gZ, 256>>>(0, NH_);
    k_zero<<<gZ, 256>>>(1, NH_);
    k_zero<<<(GG * HH + 255) / 256, 256>>>(2, NH_);

    // collapsed edge weights, tf32-split
    k_w12<147><<<147, 128>>>(f1_w1, f1_w2, p_wa_hi, p_wa_lo);
    k_w12<21><<<21, 128>>>(f2_w1, f2_w2, p_wb_hi, p_wb_lo);

    int gB = (N_ + 127) / 128;

    // xh = swish(x @ lin_w + lin_b)
    k_gemmT<false, true, false><<<gB, 256, smg>>>(x, lin_w, nullptr, nullptr, lin_b, nullptr, p_xh, N_);

    // edge GEMM + gather + scatter
    k_edgeT<147><<<148, 256, sme1>>>(feature1, p_wa_hi, p_wa_lo, edge_index, p_xh, p_agg1, E_);
    k_edgeT<21><<<592, 256, sme2>>>(feature2, p_wb_hi, p_wb_lo, edge_index, p_xh, p_agg2, E_);

    // conv1 / lin1
    k_gemmT<true, false, false><<<gB, 256, smg>>>(p_agg1, conv1_rel_w, p_xh, conv1_root_w, conv1_rel_b, nullptr, p_c, N_);
    k_gemmT<false, true, false><<<gB, 256, smg>>>(p_c, lin1_w, nullptr, nullptr, lin1_b, nullptr, p_agg1, N_);
    // conv2 / lin2
    k_gemmT<true, false, false><<<gB, 256, smg>>>(p_agg2, conv2_rel_w, p_xh, conv2_root_w, conv2_rel_b, nullptr, p_c, N_);
    k_gemmT<false, true, false><<<gB, 256, smg>>>(p_c, lin2_w, nullptr, nullptr, lin2_b, nullptr, p_agg2, N_);

    // h = cat(h1,h2) @ lincat + b + xh
    k_gemmT<true, false, true><<<gB, 256, smg>>>(p_agg1, lincat_w, p_agg2, lincat_w + HH * HH, lincat_b, p_xh, p_ha, N_);

    // residual lins: h = swish(h@W+b) + h
    k_gemmT<false, true, true><<<gB, 256, smg>>>(p_ha, lins_w,               nullptr, nullptr, lins_b,          p_ha, p_hb, N_);
    k_gemmT<false, true, true><<<gB, 256, smg>>>(p_hb, lins_w + 1 * HH * HH, nullptr, nullptr, lins_b + 1 * HH, p_hb, p_ha, N_);
    k_gemmT<false, true, true><<<gB, 256, smg>>>(p_ha, lins_w + 2 * HH * HH, nullptr, nullptr, lins_b + 2 * HH, p_ha, p_hb, N_);

    // GraphNorm
    k_gsum<<<gZ, 256>>>(p_hb, batch, N_);
    k_center<<<gZ, 256>>>(p_hb, batch, norm_ms, N_);
    k_norm<<<gZ, 256>>>(batch, norm_w, norm_b, N_);

    // final projection
    k_gemmT<false, false, false><<<gB, 256, smg>>>(p_on, final_w, nullptr, nullptr, final_b, nullptr, (float*)d_out, N_);
}